// round 7
// baseline (speedup 1.0000x reference)
#include <cuda_runtime.h>
#include <cuda_fp16.h>

#define B_ 256
#define T_ 100
#define D_ 4096
#define H_ 1024

#define BM 64
#define BN 64
#define BK 32
#define SA 40        // As row stride in halfs (conflict-free ldmatrix)
#define SBN 72       // Bs row stride in halfs (conflict-free ldmatrix.trans)
#define NTH 128
#define SPLIT1 8
#define SPLIT2 2
#define STAGES 4

// Scratch (static __device__ arrays; no dynamic allocation anywhere)
__device__ __align__(16) __half g_KFh[D_ * H_];              // KFinv fp16 [D,H]
__device__ __align__(16) __half g_Zh[H_ * D_];               // Z fp16 [H,D]
__device__ __align__(16) __half g_diffh[B_ * D_];            // x_t - nb_t, fp16
__device__ __align__(16) __half g_hidh[B_ * H_];             // hidden fp16
__device__ __align__(16) float  g_hidpart[SPLIT1 * B_ * H_]; // gemm1 split-K partials
__device__ __align__(16) float  g_g2part[SPLIT2 * B_ * D_];  // gemm2 split-K partials
__device__ unsigned g_cnt1[64];    // gemm1 per-tile counters (zero-init)
__device__ unsigned g_cnt2[256];   // gemm2 per-tile counters (zero-init)

__device__ __forceinline__ unsigned smem_u32(const void* p) {
    return (unsigned)__cvta_generic_to_shared(p);
}

__device__ __forceinline__ void cpa16(unsigned saddr, const void* g) {
    asm volatile("cp.async.cg.shared.global [%0], [%1], 16;\n" :: "r"(saddr), "l"(g));
}
__device__ __forceinline__ void cpa_commit() {
    asm volatile("cp.async.commit_group;\n");
}
__device__ __forceinline__ void cpa_wait2() {
    asm volatile("cp.async.wait_group 2;\n" ::: "memory");
}

__device__ __forceinline__ void mma16816(float* c, const unsigned* a, const unsigned* b) {
    asm volatile(
        "mma.sync.aligned.m16n8k16.row.col.f32.f16.f16.f32 "
        "{%0,%1,%2,%3},{%4,%5,%6,%7},{%8,%9},{%0,%1,%2,%3};\n"
        : "+f"(c[0]), "+f"(c[1]), "+f"(c[2]), "+f"(c[3])
        : "r"(a[0]), "r"(a[1]), "r"(a[2]), "r"(a[3]), "r"(b[0]), "r"(b[1]));
}

__device__ __forceinline__ void ldsm_x4(unsigned addr, unsigned* r) {
    asm volatile("ldmatrix.sync.aligned.m8n8.x4.shared.b16 {%0,%1,%2,%3}, [%4];\n"
        : "=r"(r[0]), "=r"(r[1]), "=r"(r[2]), "=r"(r[3]) : "r"(addr));
}
__device__ __forceinline__ void ldsm_x4_t(unsigned addr, unsigned* r) {
    asm volatile("ldmatrix.sync.aligned.m8n8.x4.trans.shared.b16 {%0,%1,%2,%3}, [%4];\n"
        : "=r"(r[0]), "=r"(r[1]), "=r"(r[2]), "=r"(r[3]) : "r"(addr));
}

// GEMM mainloop: C[64,64] += A[m0:,kbase:] * B[kbase:, n0:]
// 4 warps (2x2), warp tile 32x32, mma m16n8k16, fp32 accum.
// 4-stage cp.async pipeline, depth-2 prefetch, one __syncthreads/iter,
// next-stage loads issued BEFORE compute so they overlap it.
__device__ __forceinline__ void gemm_tile(
    const __half* __restrict__ Ag, int lda,
    const __half* __restrict__ Bg, int ldb,
    int m0, int n0, int kbase, int iters,
    float (&acc)[2][4][4])
{
    __shared__ __align__(16) __half As[STAGES][BM * SA];
    __shared__ __align__(16) __half Bs[STAGES][BK * SBN];

    const int tid = threadIdx.x;
    const int lane = tid & 31;
    const int wid = tid >> 5;
    const int wm = (wid & 1) * 32;
    const int wn = (wid >> 1) * 32;

    // Loader mapping (128 threads): A 64x32, B 32x64, 2 uint4/thread each
    const int ar = tid >> 1, ac = (tid & 1) * 16;
    const int br = tid >> 2, bc = (tid & 3) * 16;

    const __half* Abase = Ag + (m0 + ar) * lda + kbase + ac;
    const __half* Bbase = Bg + (long)(kbase + br) * ldb + n0 + bc;

    const unsigned sA = smem_u32(&As[0][ar * SA + ac]);
    const unsigned sB = smem_u32(&Bs[0][br * SBN + bc]);
    const unsigned stA = (unsigned)(BM * SA * 2);
    const unsigned stB = (unsigned)(BK * SBN * 2);

    auto issue = [&](int it) {
        const int buf = it & (STAGES - 1);
        cpa16(sA + buf * stA,      Abase + it * BK);
        cpa16(sA + buf * stA + 16, Abase + it * BK + 8);
        cpa16(sB + buf * stB,      Bbase + (long)it * BK * ldb);
        cpa16(sB + buf * stB + 16, Bbase + (long)it * BK * ldb + 8);
    };
    issue(0); cpa_commit();
    issue(1); cpa_commit();
    issue(2); cpa_commit();

    // ldmatrix per-lane address components
    const int a_row  = (lane & 7) + ((lane >> 3) & 1) * 8;
    const int a_colo = (lane >> 4) * 8;
    const int b_rowo = (lane & 7) + ((lane >> 3) & 1) * 8;
    const int b_colo = ((lane >> 4) & 1) * 8;

    for (int it = 0; it < iters; ++it) {
        cpa_wait2();          // stage `it` complete (group k <-> stage k)
        __syncthreads();
        // Issue stage it+3 NOW (its buffer was consumed at iter it-1; the
        // barrier above guarantees all threads are past that) so the loads
        // overlap this iteration's compute.
        if (it + STAGES - 1 < iters) issue(it + STAGES - 1);
        cpa_commit();         // unconditional: keeps group<->stage exact

        const __half* Asb = As[it & (STAGES - 1)];
        const __half* Bsb = Bs[it & (STAGES - 1)];
#pragma unroll
        for (int kk = 0; kk < BK; kk += 16) {
            unsigned bf[4][2];
#pragma unroll
            for (int nf2 = 0; nf2 < 2; ++nf2) {
                unsigned r[4];
                unsigned addr = smem_u32(&Bsb[(kk + b_rowo) * SBN + wn + nf2 * 16 + b_colo]);
                ldsm_x4_t(addr, r);
                bf[nf2 * 2][0]     = r[0]; bf[nf2 * 2][1]     = r[1];
                bf[nf2 * 2 + 1][0] = r[2]; bf[nf2 * 2 + 1][1] = r[3];
            }
#pragma unroll
            for (int mf = 0; mf < 2; ++mf) {
                unsigned av[4];
                unsigned addr = smem_u32(&Asb[(wm + mf * 16 + a_row) * SA + kk + a_colo]);
                ldsm_x4(addr, av);
#pragma unroll
                for (int nf = 0; nf < 4; ++nf)
                    mma16816(acc[mf][nf], av, bf[nf]);
            }
        }
    }
}

// Store register fragments as an fp32 partial tile
__device__ __forceinline__ void store_partial(float* __restrict__ outp, int ld,
                                              int m0, int n0, float (&acc)[2][4][4]) {
    const int lane = threadIdx.x & 31, wid = threadIdx.x >> 5;
    const int wm = (wid & 1) * 32, wn = (wid >> 1) * 32;
    const int r = lane >> 2, cp = (lane & 3) * 2;
#pragma unroll
    for (int mf = 0; mf < 2; ++mf)
#pragma unroll
        for (int nf = 0; nf < 4; ++nf) {
            const int m = m0 + wm + mf * 16 + r;
            const int n = n0 + wn + nf * 8 + cp;
            *(float2*)&outp[m * ld + n]       = make_float2(acc[mf][nf][0], acc[mf][nf][1]);
            *(float2*)&outp[(m + 8) * ld + n] = make_float2(acc[mf][nf][2], acc[mf][nf][3]);
        }
}

// GEMM1 (split-K=8): last-arriving CTA reduces 8 partials + b_hidden -> fp16 hidden
__global__ void __launch_bounds__(NTH, 2) gemm1_k(const float* __restrict__ bh) {
    float acc[2][4][4];
#pragma unroll
    for (int i = 0; i < 2; ++i)
#pragma unroll
        for (int j = 0; j < 4; ++j)
#pragma unroll
            for (int k = 0; k < 4; ++k) acc[i][j][k] = 0.f;

    const int m0 = blockIdx.y * BM;
    const int n0 = blockIdx.x * BN;
    const int kb = blockIdx.z * (D_ / SPLIT1);
    gemm_tile(g_diffh, D_, g_KFh, H_, m0, n0, kb, (D_ / SPLIT1) / BK, acc);

    store_partial(g_hidpart + blockIdx.z * (B_ * H_), H_, m0, n0, acc);

    __shared__ unsigned s_old;
    __threadfence();
    __syncthreads();
    if (threadIdx.x == 0)
        s_old = atomicAdd(&g_cnt1[blockIdx.y * gridDim.x + blockIdx.x], 1u);
    __syncthreads();

    if (s_old == SPLIT1 - 1) {
        __threadfence();   // acquire
        const int rr = threadIdx.x >> 1;
        const int c0 = (threadIdx.x & 1) * 32;
        const int rowbase = (m0 + rr) * H_ + n0 + c0;
#pragma unroll
        for (int j = 0; j < 8; ++j) {
            const int idx = rowbase + j * 4;
            const int n = n0 + c0 + j * 4;
            const float4 bb = *(const float4*)&bh[n];
            float s0 = bb.x, s1 = bb.y, s2 = bb.z, s3 = bb.w;
#pragma unroll
            for (int z = 0; z < SPLIT1; ++z) {   // fixed z-order: deterministic
                const float4 p = *(const float4*)&g_hidpart[idx + z * (B_ * H_)];
                s0 += p.x; s1 += p.y; s2 += p.z; s3 += p.w;
            }
            *(__half2*)&g_hidh[idx]     = __floats2half2_rn(s0, s1);
            *(__half2*)&g_hidh[idx + 2] = __floats2half2_rn(s2, s3);
        }
        if (threadIdx.x == 0)
            g_cnt1[blockIdx.y * gridDim.x + blockIdx.x] = 0;  // reset for next launch/replay
    }
}

// GEMM2 (split-K=2): last-arriving CTA reduces 2 partials + b_out, applies
// sigmoid, writes output and next step's diff = x[:,t+1,:] - nb (fp16)
__global__ void __launch_bounds__(NTH, 2) gemm2_k(const float* __restrict__ x,
                                                  const float* __restrict__ b_out,
                                                  float* __restrict__ out, int t) {
    float acc[2][4][4];
#pragma unroll
    for (int i = 0; i < 2; ++i)
#pragma unroll
        for (int j = 0; j < 4; ++j)
#pragma unroll
            for (int k = 0; k < 4; ++k) acc[i][j][k] = 0.f;

    const int m0 = blockIdx.y * BM;
    const int n0 = blockIdx.x * BN;
    const int kb = blockIdx.z * (H_ / SPLIT2);
    gemm_tile(g_hidh, H_, g_Zh, D_, m0, n0, kb, (H_ / SPLIT2) / BK, acc);

    store_partial(g_g2part + blockIdx.z * (B_ * D_), D_, m0, n0, acc);

    __shared__ unsigned s_old;
    __threadfence();
    __syncthreads();
    if (threadIdx.x == 0)
        s_old = atomicAdd(&g_cnt2[blockIdx.y * gridDim.x + blockIdx.x], 1u);
    __syncthreads();

    if (s_old == SPLIT2 - 1) {
        __threadfence();   // acquire
        const bool hasnext = (t + 1 < T_);
        const int rr = threadIdx.x >> 1;
        const int c0 = (threadIdx.x & 1) * 32;
        const int m = m0 + rr;
        const int rowbase = m * D_ + n0 + c0;
#pragma unroll
        for (int j = 0; j < 8; ++j) {
            const int idx = rowbase + j * 4;
            const int n = n0 + c0 + j * 4;
            const float4 p0 = *(const float4*)&g_g2part[idx];
            const float4 p1 = *(const float4*)&g_g2part[idx + B_ * D_];
            const float4 bb = *(const float4*)&b_out[n];
            float v0 = p0.x + p1.x + bb.x;   // fixed order: commutative+deterministic
            float v1 = p0.y + p1.y + bb.y;
            float v2 = p0.z + p1.z + bb.z;
            float v3 = p0.w + p1.w + bb.w;
            v0 = 1.f / (1.f + __expf(-v0));
            v1 = 1.f / (1.f + __expf(-v1));
            v2 = 1.f / (1.f + __expf(-v2));
            v3 = 1.f / (1.f + __expf(-v3));
            *(float4*)&out[m * (T_ * D_) + t * D_ + n] = make_float4(v0, v1, v2, v3);
            if (hasnext) {
                const float4 xv = *(const float4*)&x[m * (T_ * D_) + (t + 1) * D_ + n];
                __half2 d0 = __floats2half2_rn(xv.x - v0, xv.y - v1);
                __half2 d1 = __floats2half2_rn(xv.z - v2, xv.w - v3);
                uint2 pk;
                pk.x = *(unsigned*)&d0;
                pk.y = *(unsigned*)&d1;
                *(uint2*)&g_diffh[idx] = pk;
            }
        }
        if (threadIdx.x == 0)
            g_cnt2[blockIdx.y * gridDim.x + blockIdx.x] = 0;
    }
}

// One-time fp32 -> fp16 weight conversion
__global__ void convert_k(const float* __restrict__ Z, const float* __restrict__ KF) {
    const int i = blockIdx.x * blockDim.x + threadIdx.x;
    if (i < D_ * H_) {
        g_KFh[i] = __float2half(KF[i]);
        g_Zh[i]  = __float2half(Z[i]);
    }
}

// Step-0 diff: nb0 = b_out broadcast (no sigmoid on step 0, per reference)
__global__ void init_k(const float* __restrict__ x, const float* __restrict__ bo) {
    const int i = blockIdx.x * blockDim.x + threadIdx.x;  // over B_*D_
    const int b = i >> 12;            // D_ = 4096
    const int k = i & (D_ - 1);
    g_diffh[i] = __float2half(x[b * (T_ * D_) + k] - bo[k]);
}

extern "C" void kernel_launch(void* const* d_in, const int* in_sizes, int n_in,
                              void* d_out, int out_size) {
    const float* x  = (const float*)d_in[0];   // [B,T,D]
    const float* Z  = (const float*)d_in[1];   // [H,D]
    const float* bo = (const float*)d_in[2];   // [D]
    const float* KF = (const float*)d_in[3];   // [D,H]
    const float* bh = (const float*)d_in[4];   // [H]
    float* out = (float*)d_out;                // [B,T,D]

    convert_k<<<(D_ * H_ + 255) / 256, 256>>>(Z, KF);
    init_k<<<(B_ * D_ + 255) / 256, 256>>>(x, bo);

    dim3 g1(H_ / BN, B_ / BM, SPLIT1);  // (16, 4, 8) = 512 CTAs
    dim3 g2(D_ / BN, B_ / BM, SPLIT2);  // (64, 4, 2) = 512 CTAs
    for (int t = 0; t < T_; ++t) {
        gemm1_k<<<g1, NTH>>>(bh);
        gemm2_k<<<g2, NTH>>>(x, bo, out, t);
    }
}